// round 13
// baseline (speedup 1.0000x reference)
#include <cuda_runtime.h>
#include <cstdint>

#define NQ   4
#define DIM  16
#define NL   2
#define EDIM 512
#define E4   128
#define NTHREADS 128
#define NWARPS 4
#define TOK  4
#define NTOKENS (512*128)
#define NTILES (NTOKENS / TOK)        // 16384
#define GRID 592                       // 4 blocks/SM exactly
#define STRIDE (GRID*NWARPS)           // 2368
#define TILE_BYTES (TOK*EDIM*4)        // 8192, contiguous

typedef unsigned long long ull;

__device__ __forceinline__ ull pack2(float lo, float hi) {
    ull r; asm("mov.b64 %0, {%1,%2};" : "=l"(r) : "f"(lo), "f"(hi)); return r;
}
__device__ __forceinline__ ull dup2(float v) {
    ull r; asm("mov.b64 %0, {%1,%1};" : "=l"(r) : "f"(v)); return r;
}
__device__ __forceinline__ void unpack2(ull p, float& lo, float& hi) {
    asm("mov.b64 {%0,%1}, %2;" : "=f"(lo), "=f"(hi) : "l"(p));
}
__device__ __forceinline__ ull ffma2(ull a, ull b, ull c) {
    ull d; asm("fma.rn.f32x2 %0, %1, %2, %3;" : "=l"(d) : "l"(a), "l"(b), "l"(c));
    return d;
}
__device__ __forceinline__ void stcs2x64(void* p, ull a, ull b) {
    asm volatile("st.global.cs.v2.b64 [%0], {%1,%2};" :: "l"(p), "l"(a), "l"(b) : "memory");
}
__device__ __forceinline__ void l2_prefetch(const void* p, uint32_t bytes) {
    asm volatile("cp.async.bulk.prefetch.L2.global [%0], %1;" :: "l"(p), "r"(bytes));
}

__global__ __launch_bounds__(NTHREADS, 4)
void qlayer_fused(const float* __restrict__ x,
                  const float* __restrict__ qw,
                  const float* __restrict__ Wq,
                  const float* __restrict__ bq,
                  const float* __restrict__ Wc,
                  const float* __restrict__ bc,
                  float* __restrict__ out)
{
    __shared__ float4 sWq[NQ][E4];     // [q][e4]: 16B lane stride, conflict-free
    __shared__ float4 sWcT[NQ][E4];    // Wc transposed [q][e4]
    __shared__ float4 sbc4[E4];
    __shared__ float2 sdiag[NL][DIM];  // fused CRZ-ring diagonal
    __shared__ float2 srys[NL][NQ];
    __shared__ float  sbq[NQ];

    const int tid  = threadIdx.x;
    const int lane = tid & 31;
    const int warp = tid >> 5;

    // ---- Stage weights / constants ----
    for (int i = tid; i < NQ*E4; i += NTHREADS)
        ((float4*)sWq)[i] = ((const float4*)Wq)[i];
    {
        float* f = (float*)sWcT;
        for (int e = tid; e < EDIM; e += NTHREADS) {
            float4 r = ((const float4*)Wc)[e];
            f[0*EDIM+e] = r.x; f[1*EDIM+e] = r.y;
            f[2*EDIM+e] = r.z; f[3*EDIM+e] = r.w;
        }
    }
    for (int i = tid; i < E4; i += NTHREADS)
        sbc4[i] = ((const float4*)bc)[i];
    if (tid < NQ) sbq[tid] = bq[tid];

    if (tid < NL*DIM) {                // fused CRZ-ring diagonal
        int l = tid >> 4, k = tid & 15;
        float ang = 0.f;
        #pragma unroll
        for (int i = 0; i < NQ; i++) {
            int cb = (k >> (NQ-1-i)) & 1;
            int tb = (k >> (NQ-1-((i+1)&(NQ-1)))) & 1;
            if (cb) ang += 0.5f * qw[l*2*NQ + i] * (float)(2*tb - 1);
        }
        float sn, cs; sincosf(ang, &sn, &cs);
        sdiag[l][k] = make_float2(cs, sn);
    }
    if (tid >= 32 && tid < 32 + NL*NQ) {
        int t = tid - 32, l = t >> 2, i = t & 3;
        float sn, cs; sincosf(0.5f * qw[l*2*NQ + NQ + i], &sn, &cs);
        srys[l][i] = make_float2(cs, sn);
    }
    __syncthreads();

    const float bq0 = sbq[0], bq1 = sbq[1], bq2 = sbq[2], bq3 = sbq[3];
    const float4* __restrict__ x4 = (const float4*)x;
    float4* __restrict__ out4 = (float4*)out;

    const int gwid = blockIdx.x * NWARPS + warp;
    const bool late_prefetch = (warp & 1);   // 2-phase stagger (R11-best)

    float4 xbuf[16];    // 4 tokens x 4 chunks: pipeline buffer

#define PREFETCH_NEXT(TI) do {                                             \
        int _n = (TI) + STRIDE; if (_n > NTILES-1) _n = NTILES-1;          \
        const size_t _b = (size_t)_n * TOK * E4 + lane;                    \
        _Pragma("unroll")                                                  \
        for (int _t = 0; _t < TOK; _t++)                                   \
            _Pragma("unroll")                                              \
            for (int _c = 0; _c < 4; _c++)                                 \
                xbuf[_t*4+_c] = __ldcs(&x4[_b + (size_t)_t*E4 + _c*32]);   \
    } while (0)

    // ---- Prologue: bulk-prefetch tile+STRIDE into L2, load first tile ----
    int tile = gwid;
    if (tile < NTILES) {
        if (lane == 0) {
            int n1 = tile + STRIDE; if (n1 > NTILES-1) n1 = NTILES-1;
            l2_prefetch((const char*)x + (size_t)n1 * TILE_BYTES, TILE_BYTES);
        }
        const size_t base = (size_t)tile * TOK * E4 + lane;
        #pragma unroll
        for (int t = 0; t < TOK; t++)
            #pragma unroll
            for (int c = 0; c < 4; c++)
                xbuf[t*4+c] = __ldcs(&x4[base + (size_t)t*E4 + c*32]);
    }

    #pragma unroll 1
    for (; tile < NTILES; tile += STRIDE) {
        // ---- Async engine: pull tile+2*STRIDE into L2 (zero reg cost) ----
        if (lane == 0) {
            int pf = tile + 2*STRIDE; if (pf > NTILES-1) pf = NTILES-1;
            l2_prefetch((const char*)x + (size_t)pf * TILE_BYTES, TILE_BYTES);
        }

        // ---- Consume buffer: f32x2 partial dots (frees xbuf) ----
        ull acc[16];                       // [t*4+q], packed adjacent-e pairs
        #pragma unroll
        for (int i = 0; i < 16; i++) acc[i] = 0ull;
        #pragma unroll
        for (int c = 0; c < 4; c++) {
            const int j4 = c*32 + lane;
            const ulonglong2 w0 = *(const ulonglong2*)&sWq[0][j4];
            const ulonglong2 w1 = *(const ulonglong2*)&sWq[1][j4];
            const ulonglong2 w2 = *(const ulonglong2*)&sWq[2][j4];
            const ulonglong2 w3 = *(const ulonglong2*)&sWq[3][j4];
            #pragma unroll
            for (int t = 0; t < TOK; t++) {
                float4 xv = xbuf[t*4+c];
                ull xl = pack2(xv.x, xv.y);
                ull xh = pack2(xv.z, xv.w);
                acc[t*4+0] = ffma2(xl, w0.x, ffma2(xh, w0.y, acc[t*4+0]));
                acc[t*4+1] = ffma2(xl, w1.x, ffma2(xh, w1.y, acc[t*4+1]));
                acc[t*4+2] = ffma2(xl, w2.x, ffma2(xh, w2.y, acc[t*4+2]));
                acc[t*4+3] = ffma2(xl, w3.x, ffma2(xh, w3.y, acc[t*4+3]));
            }
        }

        // ---- Even warps: LDG-prefetch tile+STRIDE now (L2-hit latency) ----
        if (!late_prefetch) PREFETCH_NEXT(tile);

        // ---- Horizontal add + tree reduction 16 -> 1 per lane ----
        float v16[16];
        #pragma unroll
        for (int i = 0; i < 16; i++) {
            float lo, hi; unpack2(acc[i], lo, hi);
            v16[i] = lo + hi;
        }
        float v8[8];
        {
            const bool hi = (lane & 16) != 0;
            #pragma unroll
            for (int i = 0; i < 8; i++) {
                float mine = hi ? v16[i+8] : v16[i];
                float send = hi ? v16[i]   : v16[i+8];
                v8[i] = mine + __shfl_xor_sync(0xffffffffu, send, 16);
            }
        }
        float v4_[4];
        {
            const bool hi = (lane & 8) != 0;
            #pragma unroll
            for (int i = 0; i < 4; i++) {
                float mine = hi ? v8[i+4] : v8[i];
                float send = hi ? v8[i]   : v8[i+4];
                v4_[i] = mine + __shfl_xor_sync(0xffffffffu, send, 8);
            }
        }
        float v2_[2];
        {
            const bool hi = (lane & 4) != 0;
            #pragma unroll
            for (int i = 0; i < 2; i++) {
                float m2 = hi ? v4_[i+2] : v4_[i];
                float s2 = hi ? v4_[i]   : v4_[i+2];
                v2_[i] = m2 + __shfl_xor_sync(0xffffffffu, s2, 4);
            }
        }
        float v1;
        {
            const bool hi = (lane & 2) != 0;
            float mine = hi ? v2_[1] : v2_[0];
            float send = hi ? v2_[0] : v2_[1];
            v1 = mine + __shfl_xor_sync(0xffffffffu, send, 2);
        }
        v1 += __shfl_xor_sync(0xffffffffu, v1, 1);
        const int tl = lane & 3;
        float gx  = __shfl_sync(0xffffffffu, v1, 8*tl + 0);
        float gy  = __shfl_sync(0xffffffffu, v1, 8*tl + 2);
        float gz  = __shfl_sync(0xffffffffu, v1, 8*tl + 4);
        float gw_ = __shfl_sync(0xffffffffu, v1, 8*tl + 6);

        // ---- Odd warps: LDG-prefetch here (stagger) ----
        if (late_prefetch) PREFETCH_NEXT(tile);

        // ---- Circuit on lanes 0..3 (one token per lane) ----
        float z0 = 0.f, z1 = 0.f, z2 = 0.f, z3 = 0.f;
        if (lane < TOK) {
            float c_[4], s_[4];
            __sincosf(0.5f*(gx + bq0),  &s_[0], &c_[0]);
            __sincosf(0.5f*(gy + bq1),  &s_[1], &c_[1]);
            __sincosf(0.5f*(gz + bq2),  &s_[2], &c_[2]);
            __sincosf(0.5f*(gw_ + bq3), &s_[3], &c_[3]);

            float2 st[DIM];
            #pragma unroll
            for (int k = 0; k < DIM; k++) {
                float m = 1.f; int p = 0;
                #pragma unroll
                for (int w = 0; w < NQ; w++) {
                    if ((k >> (NQ-1-w)) & 1) { m *= s_[w]; p++; }
                    else                     { m *= c_[w]; }
                }
                float re, im;
                switch (p & 3) {
                    case 0:  re =  m; im = 0.f; break;
                    case 1:  re = 0.f; im = -m; break;
                    case 2:  re = -m; im = 0.f; break;
                    default: re = 0.f; im =  m; break;
                }
                st[k] = make_float2(re, im);
            }
            #pragma unroll
            for (int l = 0; l < NL; l++) {
                #pragma unroll
                for (int k = 0; k < DIM; k++) {
                    float2 d = sdiag[l][k];
                    float re = st[k].x*d.x - st[k].y*d.y;
                    float im = st[k].x*d.y + st[k].y*d.x;
                    st[k].x = re; st[k].y = im;
                }
                #pragma unroll
                for (int i = 0; i < NQ; i++) {
                    float2 cs = srys[l][i];
                    const int S = 1 << (NQ-1-i);
                    #pragma unroll
                    for (int k = 0; k < DIM; k++) {
                        if (k & S) continue;
                        float2 a0 = st[k], a1 = st[k|S];
                        st[k].x   = cs.x*a0.x - cs.y*a1.x;
                        st[k].y   = cs.x*a0.y - cs.y*a1.y;
                        st[k|S].x = cs.y*a0.x + cs.x*a1.x;
                        st[k|S].y = cs.y*a0.y + cs.x*a1.y;
                    }
                }
            }
            #pragma unroll
            for (int k = 0; k < DIM; k++) {
                float p = st[k].x*st[k].x + st[k].y*st[k].y;
                z0 += (k & 8) ? -p : p;
                z1 += (k & 4) ? -p : p;
                z2 += (k & 2) ? -p : p;
                z3 += (k & 1) ? -p : p;
            }
        }

        // ---- Broadcast q_out once (lane m holds token m, m in 0..3) ----
        ull dqx[TOK], dqy[TOK], dqz[TOK], dqe[TOK];
        #pragma unroll
        for (int m = 0; m < TOK; m++) {
            dqx[m] = dup2(__shfl_sync(0xffffffffu, z0, m));
            dqy[m] = dup2(__shfl_sync(0xffffffffu, z1, m));
            dqz[m] = dup2(__shfl_sync(0xffffffffu, z2, m));
            dqe[m] = dup2(__shfl_sync(0xffffffffu, z3, m));
        }

        // ---- Store: packed out = q_out . Wc^T + bc ----
        const size_t obase = (size_t)tile * TOK * E4;
        #pragma unroll
        for (int c = 0; c < 4; c++) {
            const int e4 = c*32 + lane;
            const ulonglong2 w0 = ((const ulonglong2*)sWcT[0])[e4];
            const ulonglong2 w1 = ((const ulonglong2*)sWcT[1])[e4];
            const ulonglong2 w2 = ((const ulonglong2*)sWcT[2])[e4];
            const ulonglong2 w3 = ((const ulonglong2*)sWcT[3])[e4];
            const ulonglong2 bb = ((const ulonglong2*)sbc4)[e4];
            #pragma unroll
            for (int m = 0; m < TOK; m++) {
                ull axy = bb.x, azw = bb.y;
                axy = ffma2(dqx[m], w0.x, axy);  azw = ffma2(dqx[m], w0.y, azw);
                axy = ffma2(dqy[m], w1.x, axy);  azw = ffma2(dqy[m], w1.y, azw);
                axy = ffma2(dqz[m], w2.x, axy);  azw = ffma2(dqz[m], w2.y, azw);
                axy = ffma2(dqe[m], w3.x, axy);  azw = ffma2(dqe[m], w3.y, azw);
                stcs2x64(&out4[obase + (size_t)m*E4 + e4], axy, azw);
            }
        }
    }
#undef PREFETCH_NEXT
}

extern "C" void kernel_launch(void* const* d_in, const int* in_sizes, int n_in,
                              void* d_out, int out_size) {
    const float* x  = (const float*)d_in[0];
    const float* qw = (const float*)d_in[1];
    const float* Wq = (const float*)d_in[2];
    const float* bq = (const float*)d_in[3];
    const float* Wc = (const float*)d_in[4];
    const float* bc = (const float*)d_in[5];
    float* out = (float*)d_out;

    qlayer_fused<<<GRID, NTHREADS>>>(x, qw, Wq, bq, Wc, bc, out);
}

// round 14
// speedup vs baseline: 1.1054x; 1.1054x over previous
#include <cuda_runtime.h>
#include <cstdint>

#define NQ   4
#define DIM  16
#define NL   2
#define EDIM 512
#define E4   128
#define NTHREADS 64
#define TOK  4                         // tokens per subtile
#define NSUB 8                         // subtiles per warp group (32 tokens)
#define NTOKENS (512*128)
#define GRID (NTOKENS/(NTHREADS/32)/(TOK*NSUB)/16*16)  // 1024

typedef unsigned long long ull;

__device__ __forceinline__ ull pack2(float lo, float hi) {
    ull r; asm("mov.b64 %0, {%1,%2};" : "=l"(r) : "f"(lo), "f"(hi)); return r;
}
__device__ __forceinline__ ull dup2(float v) {
    ull r; asm("mov.b64 %0, {%1,%1};" : "=l"(r) : "f"(v)); return r;
}
__device__ __forceinline__ void unpack2(ull p, float& lo, float& hi) {
    asm("mov.b64 {%0,%1}, %2;" : "=f"(lo), "=f"(hi) : "l"(p));
}
__device__ __forceinline__ ull ffma2(ull a, ull b, ull c) {
    ull d; asm("fma.rn.f32x2 %0, %1, %2, %3;" : "=l"(d) : "l"(a), "l"(b), "l"(c));
    return d;
}
__device__ __forceinline__ void stcs2x64(void* p, ull a, ull b) {
    asm volatile("st.global.cs.v2.b64 [%0], {%1,%2};" :: "l"(p), "l"(a), "l"(b) : "memory");
}

__global__ __launch_bounds__(NTHREADS)
void qlayer_fused(const float* __restrict__ x,
                  const float* __restrict__ qw,
                  const float* __restrict__ Wq,
                  const float* __restrict__ bq,
                  const float* __restrict__ Wc,
                  const float* __restrict__ bc,
                  float* __restrict__ out)
{
    __shared__ float4 sWq[NQ][E4];     // conflict-free: 16B lane stride
    __shared__ float4 sWcT[NQ][E4];    // Wc transposed [q][e4]
    __shared__ float4 sbc4[E4];
    __shared__ float2 sdiag[NL][DIM];  // fused CRZ-ring diagonal
    __shared__ float2 srys[NL][NQ];
    __shared__ float  sbq[NQ];

    const int tid  = threadIdx.x;
    const int lane = tid & 31;
    const int warp = tid >> 5;

    // ---- Stage weights / constants (64 threads) ----
    for (int i = tid; i < NQ*E4; i += NTHREADS)
        ((float4*)sWq)[i] = ((const float4*)Wq)[i];
    {
        float* f = (float*)sWcT;
        for (int e = tid; e < EDIM; e += NTHREADS) {
            float4 r = ((const float4*)Wc)[e];
            f[0*EDIM+e] = r.x; f[1*EDIM+e] = r.y;
            f[2*EDIM+e] = r.z; f[3*EDIM+e] = r.w;
        }
    }
    for (int i = tid; i < E4; i += NTHREADS)
        sbc4[i] = ((const float4*)bc)[i];
    if (tid < NQ) sbq[tid] = bq[tid];

    if (tid < NL*DIM) {                // fused CRZ-ring diagonal
        int l = tid >> 4, k = tid & 15;
        float ang = 0.f;
        #pragma unroll
        for (int i = 0; i < NQ; i++) {
            int cb = (k >> (NQ-1-i)) & 1;
            int tb = (k >> (NQ-1-((i+1)&(NQ-1)))) & 1;
            if (cb) ang += 0.5f * qw[l*2*NQ + i] * (float)(2*tb - 1);
        }
        float sn, cs; sincosf(ang, &sn, &cs);
        sdiag[l][k] = make_float2(cs, sn);
    }
    if (tid >= 32 && tid < 32 + NL*NQ) {
        int t = tid - 32, l = t >> 2, i = t & 3;
        float sn, cs; sincosf(0.5f * qw[l*2*NQ + NQ + i], &sn, &cs);
        srys[l][i] = make_float2(cs, sn);
    }
    __syncthreads();

    const float bq0 = sbq[0], bq1 = sbq[1], bq2 = sbq[2], bq3 = sbq[3];
    const float4* __restrict__ x4 = (const float4*)x;
    float4* __restrict__ out4 = (float4*)out;

    const int gw = blockIdx.x * 2 + warp;           // global warp id, 2048 total
    const size_t tokBase = (size_t)gw * (TOK*NSUB); // 32 tokens per warp

    float4 xbuf[16];    // one subtile (4 tokens x 4 chunks)

#define LOAD_SUB(G) do {                                                   \
        const size_t _b = (tokBase + (G)*TOK) * E4 + lane;                 \
        _Pragma("unroll")                                                  \
        for (int _t = 0; _t < TOK; _t++)                                   \
            _Pragma("unroll")                                              \
            for (int _c = 0; _c < 4; _c++)                                 \
                xbuf[_t*4+_c] = __ldcs(&x4[_b + (size_t)_t*E4 + _c*32]);   \
    } while (0)

    // ---- Prologue: load subtile 0 ----
    LOAD_SUB(0);

    // ========== Pass 1: 8x (consume -> prefetch -> tree), park angles ==========
    float4 qin;   // each lane ends with one token's angles (lane = 4g+m)
    #pragma unroll 1
    for (int g = 0; g < NSUB; g++) {
        // ---- Consume: f32x2 partial dots (frees xbuf) ----
        ull acc[16];
        #pragma unroll
        for (int i = 0; i < 16; i++) acc[i] = 0ull;
        #pragma unroll
        for (int c = 0; c < 4; c++) {
            const int j4 = c*32 + lane;
            const ulonglong2 w0 = *(const ulonglong2*)&sWq[0][j4];
            const ulonglong2 w1 = *(const ulonglong2*)&sWq[1][j4];
            const ulonglong2 w2 = *(const ulonglong2*)&sWq[2][j4];
            const ulonglong2 w3 = *(const ulonglong2*)&sWq[3][j4];
            #pragma unroll
            for (int t = 0; t < TOK; t++) {
                float4 xv = xbuf[t*4+c];
                ull xl = pack2(xv.x, xv.y);
                ull xh = pack2(xv.z, xv.w);
                acc[t*4+0] = ffma2(xl, w0.x, ffma2(xh, w0.y, acc[t*4+0]));
                acc[t*4+1] = ffma2(xl, w1.x, ffma2(xh, w1.y, acc[t*4+1]));
                acc[t*4+2] = ffma2(xl, w2.x, ffma2(xh, w2.y, acc[t*4+2]));
                acc[t*4+3] = ffma2(xl, w3.x, ffma2(xh, w3.y, acc[t*4+3]));
            }
        }

        // ---- Prefetch next subtile (in flight through tree) ----
        if (g < NSUB-1) LOAD_SUB(g+1);

        // ---- Horizontal add + tree reduction 16 -> 1 per lane ----
        float v16[16];
        #pragma unroll
        for (int i = 0; i < 16; i++) {
            float lo, hi; unpack2(acc[i], lo, hi);
            v16[i] = lo + hi;
        }
        float v8[8];
        {
            const bool hi = (lane & 16) != 0;
            #pragma unroll
            for (int i = 0; i < 8; i++) {
                float mine = hi ? v16[i+8] : v16[i];
                float send = hi ? v16[i]   : v16[i+8];
                v8[i] = mine + __shfl_xor_sync(0xffffffffu, send, 16);
            }
        }
        float v4_[4];
        {
            const bool hi = (lane & 8) != 0;
            #pragma unroll
            for (int i = 0; i < 4; i++) {
                float mine = hi ? v8[i+4] : v8[i];
                float send = hi ? v8[i]   : v8[i+4];
                v4_[i] = mine + __shfl_xor_sync(0xffffffffu, send, 8);
            }
        }
        float v2_[2];
        {
            const bool hi = (lane & 4) != 0;
            #pragma unroll
            for (int i = 0; i < 2; i++) {
                float m2 = hi ? v4_[i+2] : v4_[i];
                float s2 = hi ? v4_[i]   : v4_[i+2];
                v2_[i] = m2 + __shfl_xor_sync(0xffffffffu, s2, 4);
            }
        }
        float v1;
        {
            const bool hi = (lane & 2) != 0;
            float mine = hi ? v2_[1] : v2_[0];
            float send = hi ? v2_[0] : v2_[1];
            v1 = mine + __shfl_xor_sync(0xffffffffu, send, 2);
        }
        v1 += __shfl_xor_sync(0xffffffffu, v1, 1);
        // lane L holds (t = L>>3, q = 2*((L>>2)&1)+((L>>1)&1))
        const int tl = lane & 3;
        float gx  = __shfl_sync(0xffffffffu, v1, 8*tl + 0);
        float gy  = __shfl_sync(0xffffffffu, v1, 8*tl + 2);
        float gz  = __shfl_sync(0xffffffffu, v1, 8*tl + 4);
        float gw_ = __shfl_sync(0xffffffffu, v1, 8*tl + 6);

        // park group g's 4 tokens on lanes 4g..4g+3 (token = lane&3)
        if ((lane >> 2) == g)
            qin = make_float4(gx + bq0, gy + bq1, gz + bq2, gw_ + bq3);
    }

    // ========== Circuit: DENSE — one token per lane, all 32 lanes ==========
    float z0 = 0.f, z1 = 0.f, z2 = 0.f, z3 = 0.f;
    {
        float c_[4], s_[4];
        __sincosf(0.5f*qin.x, &s_[0], &c_[0]);
        __sincosf(0.5f*qin.y, &s_[1], &c_[1]);
        __sincosf(0.5f*qin.z, &s_[2], &c_[2]);
        __sincosf(0.5f*qin.w, &s_[3], &c_[3]);

        float2 st[DIM];
        #pragma unroll
        for (int k = 0; k < DIM; k++) {
            float m = 1.f; int p = 0;
            #pragma unroll
            for (int w = 0; w < NQ; w++) {
                if ((k >> (NQ-1-w)) & 1) { m *= s_[w]; p++; }
                else                     { m *= c_[w]; }
            }
            float re, im;
            switch (p & 3) {
                case 0:  re =  m; im = 0.f; break;
                case 1:  re = 0.f; im = -m; break;
                case 2:  re = -m; im = 0.f; break;
                default: re = 0.f; im =  m; break;
            }
            st[k] = make_float2(re, im);
        }
        #pragma unroll
        for (int l = 0; l < NL; l++) {
            #pragma unroll
            for (int k = 0; k < DIM; k++) {
                float2 d = sdiag[l][k];
                float re = st[k].x*d.x - st[k].y*d.y;
                float im = st[k].x*d.y + st[k].y*d.x;
                st[k].x = re; st[k].y = im;
            }
            #pragma unroll
            for (int i = 0; i < NQ; i++) {
                float2 cs = srys[l][i];
                const int S = 1 << (NQ-1-i);
                #pragma unroll
                for (int k = 0; k < DIM; k++) {
                    if (k & S) continue;
                    float2 a0 = st[k], a1 = st[k|S];
                    st[k].x   = cs.x*a0.x - cs.y*a1.x;
                    st[k].y   = cs.x*a0.y - cs.y*a1.y;
                    st[k|S].x = cs.y*a0.x + cs.x*a1.x;
                    st[k|S].y = cs.y*a0.y + cs.x*a1.y;
                }
            }
        }
        #pragma unroll
        for (int k = 0; k < DIM; k++) {
            float p = st[k].x*st[k].x + st[k].y*st[k].y;
            z0 += (k & 8) ? -p : p;
            z1 += (k & 4) ? -p : p;
            z2 += (k & 2) ? -p : p;
            z3 += (k & 1) ? -p : p;
        }
    }

    // ========== Pass 2: 8x broadcast + store ==========
    #pragma unroll 1
    for (int g = 0; g < NSUB; g++) {
        // token m of subtile g lives on lane 4g+m
        ull dqx[TOK], dqy[TOK], dqz[TOK], dqe[TOK];
        #pragma unroll
        for (int m = 0; m < TOK; m++) {
            dqx[m] = dup2(__shfl_sync(0xffffffffu, z0, 4*g + m));
            dqy[m] = dup2(__shfl_sync(0xffffffffu, z1, 4*g + m));
            dqz[m] = dup2(__shfl_sync(0xffffffffu, z2, 4*g + m));
            dqe[m] = dup2(__shfl_sync(0xffffffffu, z3, 4*g + m));
        }
        const size_t obase = (tokBase + (size_t)g*TOK) * E4;
        #pragma unroll
        for (int c = 0; c < 4; c++) {
            const int e4 = c*32 + lane;
            const ulonglong2 w0 = ((const ulonglong2*)sWcT[0])[e4];
            const ulonglong2 w1 = ((const ulonglong2*)sWcT[1])[e4];
            const ulonglong2 w2 = ((const ulonglong2*)sWcT[2])[e4];
            const ulonglong2 w3 = ((const ulonglong2*)sWcT[3])[e4];
            const ulonglong2 bb = ((const ulonglong2*)sbc4)[e4];
            #pragma unroll
            for (int m = 0; m < TOK; m++) {
                ull axy = bb.x, azw = bb.y;
                axy = ffma2(dqx[m], w0.x, axy);  azw = ffma2(dqx[m], w0.y, azw);
                axy = ffma2(dqy[m], w1.x, axy);  azw = ffma2(dqy[m], w1.y, azw);
                axy = ffma2(dqz[m], w2.x, axy);  azw = ffma2(dqz[m], w2.y, azw);
                axy = ffma2(dqe[m], w3.x, axy);  azw = ffma2(dqe[m], w3.y, azw);
                stcs2x64(&out4[obase + (size_t)m*E4 + e4], axy, azw);
            }
        }
    }
#undef LOAD_SUB
}

extern "C" void kernel_launch(void* const* d_in, const int* in_sizes, int n_in,
                              void* d_out, int out_size) {
    const float* x  = (const float*)d_in[0];
    const float* qw = (const float*)d_in[1];
    const float* Wq = (const float*)d_in[2];
    const float* bq = (const float*)d_in[3];
    const float* Wc = (const float*)d_in[4];
    const float* bc = (const float*)d_in[5];
    float* out = (float*)d_out;

    qlayer_fused<<<1024, NTHREADS>>>(x, qw, Wq, bq, Wc, bc, out);   // 2048 warps x 32 tokens
}